// round 13
// baseline (speedup 1.0000x reference)
#include <cuda_runtime.h>
#include <math.h>

#define T_  512
#define B_  2048
#define I_  24
#define H_  20

// Scratch xg[t][b][u] = float4(i,f,g,o). 8 pad timesteps so recur's depth-2
// prefetch stays in-bounds.
__device__ float4 g_xg[(size_t)(T_ + 8) * B_ * H_];
// h[t][b][u] for the head pass.
__device__ float  g_h[(size_t)T_ * B_ * H_];

__device__ __forceinline__ float tanhx(float x) {
    float r; asm("tanh.approx.f32 %0,%1;" : "=f"(r) : "f"(x)); return r;
}
__device__ __forceinline__ float sigx(float x) {   // sigmoid via HW tanh
    return fmaf(0.5f, tanhx(0.5f * x), 0.5f);
}

// ---------------------------------------------------------------------------
// Kernel 1: xg = x @ W_ih^T + (b_ih+b_hh) for t < len[b].
// Thread = (column j 0..3, unit u, gate-pair p). Software-pipelined over t
// (x[t+1] in a separate register buffer). Each gate output accumulates in
// TWO 12-deep chains (crit path 96->48 cyc). Coalesced float2 stores into
// recur's [t][b][u] layout.
// ---------------------------------------------------------------------------
#define XG_CHUNK 64
__global__ __launch_bounds__(160, 3)
void xg_kernel(const float* __restrict__ x,
               const int*   __restrict__ lens,
               const float* __restrict__ Wih,
               const float* __restrict__ bih,
               const float* __restrict__ bhh)
{
    const int slab = blockIdx.x >> 3;         // 0..511 (4 b each)
    const int chn  = blockIdx.x & 7;          // 0..7
    const int t0   = chn * XG_CHUNK;
    const int b0   = slab * 4;

    const int lmax = lens[b0];                // max length in slab (sorted)
    if (t0 >= lmax) return;                   // whole chunk masked
    const int tend = min(t0 + XG_CHUNK, lmax);

    const int tid = threadIdx.x;
    const int j   = tid / 40;                 // column 0..3
    const int r   = tid % 40;
    const int u   = r >> 1;                   // unit 0..19
    const int p   = r & 1;                    // gate pair: 0=(i,f) 1=(g,o)
    const int b   = b0 + j;
    const int mylen = lens[b];

    const int g0 = 2 * p, g1 = 2 * p + 1;
    float w0[I_], w1[I_];
    #pragma unroll
    for (int k = 0; k < I_; k++) {
        w0[k] = Wih[(g0 * H_ + u) * I_ + k];
        w1[k] = Wih[(g1 * H_ + u) * I_ + k];
    }
    float2 bias;
    bias.x = bih[g0 * H_ + u] + bhh[g0 * H_ + u];
    bias.y = bih[g1 * H_ + u] + bhh[g1 * H_ + u];

    const size_t xstr = (size_t)B_ * I_ / 4;              // per-t, in float4s
    const size_t ostr = (size_t)B_ * H_ * 2;              // per-t, in float2s
    const float4* xbase = (const float4*)(x + (size_t)b * I_);
    float2* op = (float2*)g_xg + ((size_t)t0 * B_ + b) * H_ * 2 + u * 2 + p;

    float4 c0, c1, c2, c3, c4, c5;            // current x[t]
    {
        const float4* pc = xbase + (size_t)t0 * xstr;
        c0 = pc[0]; c1 = pc[1]; c2 = pc[2];
        c3 = pc[3]; c4 = pc[4]; c5 = pc[5];
    }

    #pragma unroll 2
    for (int t = t0; t < tend; t++) {
        const float4* pn = xbase + (size_t)min(t + 1, T_ - 1) * xstr;
        float4 n0 = pn[0], n1 = pn[1], n2 = pn[2];
        float4 n3 = pn[3], n4 = pn[4], n5 = pn[5];

        const float xv[I_] = { c0.x,c0.y,c0.z,c0.w, c1.x,c1.y,c1.z,c1.w,
                               c2.x,c2.y,c2.z,c2.w, c3.x,c3.y,c3.z,c3.w,
                               c4.x,c4.y,c4.z,c4.w, c5.x,c5.y,c5.z,c5.w };
        // two 12-deep chains per gate output
        float ax0 = bias.x, ax1 = 0.0f, ay0 = bias.y, ay1 = 0.0f;
        #pragma unroll
        for (int k = 0; k < I_; k += 2) {
            ax0 = fmaf(w0[k],   xv[k],   ax0);
            ax1 = fmaf(w0[k+1], xv[k+1], ax1);
            ay0 = fmaf(w1[k],   xv[k],   ay0);
            ay1 = fmaf(w1[k+1], xv[k+1], ay1);
        }

        if (t < mylen) *op = make_float2(ax0 + ax1, ay0 + ay1);
        op += ostr;

        c0 = n0; c1 = n1; c2 = n2; c3 = n3; c4 = n4; c5 = n5;
    }
}

// ---------------------------------------------------------------------------
// Kernel 2: recurrence — TWO independent sequences per warp (bA = w long,
// bB = 2047-w short; lenA >= lenB, lenA+lenB ~ const). Weight registers are
// shared (they depend only on the lane's unit), so the second stream costs
// no regs but doubles the independent dependency chains per warp -> hides
// the SHFL+FMA+tanh critical path that left issue at ~35%. Stream-B steps
// are warp-uniformly guarded by t < lenB. Depth-2 prefetch per stream.
// ---------------------------------------------------------------------------
__global__ __launch_bounds__(128, 3)
void recur_kernel(const int*   __restrict__ lens,
                  const float* __restrict__ Whh)
{
    const int lane = threadIdx.x & 31;
    const int wid  = threadIdx.x >> 5;
    const int w    = blockIdx.x * 4 + wid;        // 0..1023
    const int bA   = w;                           // long sequence
    const int bB   = 2047 - w;                    // short sequence
    const int uu   = (lane < H_) ? lane : 0;      // lanes 20..31 mirror u=0

    float wi[H_], wf[H_], wg[H_], wo[H_];
    #pragma unroll
    for (int k = 0; k < H_; k++) {
        wi[k] = Whh[(0*H_ + uu) * H_ + k];
        wf[k] = Whh[(1*H_ + uu) * H_ + k];
        wg[k] = Whh[(2*H_ + uu) * H_ + k];
        wo[k] = Whh[(3*H_ + uu) * H_ + k];
    }
    const int lenA = lens[bA];                    // >= lenB >= 1
    const int lenB = lens[bB];

    float hA = 0.0f, cA = 0.0f, hB = 0.0f, cB = 0.0f;

    const size_t xstride = (size_t)B_ * H_;
    const float4* xpA = &g_xg[(size_t)bA * H_ + uu];
    const float4* xpB = &g_xg[(size_t)bB * H_ + uu];
    float4 qA0 = xpA[0], qA1 = xpA[xstride];
    float4 qB0 = xpB[0], qB1 = xpB[xstride];
    xpA += 2 * xstride;
    xpB += 2 * xstride;

    float* hpA = &g_h[(size_t)bA * H_ + lane];
    float* hpB = &g_h[(size_t)bB * H_ + lane];

    #define RSTEP(QBUF, XP, HVAR, CVAR, HP, TT)                          \
    {                                                                    \
        float ai = QBUF.x, af = QBUF.y, ag = QBUF.z, ao = QBUF.w;        \
        _Pragma("unroll")                                                \
        for (int k = 0; k < H_; k++) {                                   \
            float hk = __shfl_sync(0xffffffffu, HVAR, k);                \
            ai = fmaf(wi[k], hk, ai);                                    \
            af = fmaf(wf[k], hk, af);                                    \
            ag = fmaf(wg[k], hk, ag);                                    \
            ao = fmaf(wo[k], hk, ao);                                    \
        }                                                                \
        CVAR = fmaf(sigx(af), CVAR, sigx(ai) * tanhx(ag));               \
        HVAR = sigx(ao) * tanhx(CVAR);                                   \
        if (lane < H_) HP[(size_t)(TT) * (B_ * H_)] = HVAR;              \
        QBUF = *XP;                               /* refill TT+2 */      \
        XP += xstride;                                                   \
    }

    for (int t = 0; t < lenA; t += 2) {
        RSTEP(qA0, xpA, hA, cA, hpA, t)
        if (t < lenB)     RSTEP(qB0, xpB, hB, cB, hpB, t)
        else              { qB0 = *xpB; xpB += xstride; }
        RSTEP(qA1, xpA, hA, cA, hpA, t + 1)
        if (t + 1 < lenB) RSTEP(qB1, xpB, hB, cB, hpB, t + 1)
        else              { qB1 = *xpB; xpB += xstride; }
    }
    #undef RSTEP
}

// ---------------------------------------------------------------------------
// Kernel 3: heads + padding over the full [T, B] grid.
// ---------------------------------------------------------------------------
__global__ __launch_bounds__(256)
void head_kernel(const int*   __restrict__ lens,
                 const float* __restrict__ Wa,
                 const float* __restrict__ ba,
                 const float* __restrict__ Wb,
                 const float* __restrict__ bb,
                 float* __restrict__ out)
{
    const int idx = blockIdx.x * 256 + threadIdx.x;   // t*B + b
    const int b   = idx & (B_ - 1);
    const int t   = idx >> 11;

    float za = ba[0], zb = bb[0];
    if (t < lens[b]) {
        float4 hq[5];
        const float4* hp = (const float4*)&g_h[(size_t)idx * H_];
        #pragma unroll
        for (int q = 0; q < 5; q++) hq[q] = hp[q];
        const float* hv = (const float*)hq;
        #pragma unroll
        for (int k = 0; k < H_; k++) {
            za = fmaf(hv[k], Wa[k], za);
            zb = fmaf(hv[k], Wb[k], zb);
        }
    }
    out[idx] = __expf(za);
    out[(size_t)T_ * B_ + idx] =
        fmaxf(zb, 0.0f) + __logf(1.0f + __expf(-fabsf(zb)));
}

extern "C" void kernel_launch(void* const* d_in, const int* in_sizes, int n_in,
                              void* d_out, int out_size)
{
    const float *x = 0, *Wih = 0, *Whh = 0, *bih = 0, *bhh = 0;
    const float *Wa = 0, *ba = 0, *Wb = 0, *bb = 0;
    const int *lens = 0;
    int seen80 = 0, seen20 = 0, seen1 = 0;
    for (int i = 0; i < n_in; i++) {
        int s = in_sizes[i];
        if      (s == T_ * B_ * I_) x    = (const float*)d_in[i];
        else if (s == B_)           lens = (const int*)d_in[i];
        else if (s == 4*H_ * I_)    Wih  = (const float*)d_in[i];
        else if (s == 4*H_ * H_)    Whh  = (const float*)d_in[i];
        else if (s == 4*H_) { if (seen80++ == 0) bih = (const float*)d_in[i]; else bhh = (const float*)d_in[i]; }
        else if (s == H_)   { if (seen20++ == 0) Wa  = (const float*)d_in[i]; else Wb  = (const float*)d_in[i]; }
        else if (s == 1)    { if (seen1++  == 0) ba  = (const float*)d_in[i]; else bb  = (const float*)d_in[i]; }
    }

    float* out = (float*)d_out;
    xg_kernel<<<512 * 8, 160>>>(x, lens, Wih, bih, bhh);
    recur_kernel<<<256, 128>>>(lens, Whh);
    head_kernel<<<(T_ * B_) / 256, 256>>>(lens, Wa, ba, Wb, bb, out);
}

// round 14
// speedup vs baseline: 1.0823x; 1.0823x over previous
#include <cuda_runtime.h>
#include <math.h>

#define T_  512
#define B_  2048
#define I_  24
#define H_  20

// Scratch xg[t][b][u] = float4(i,f,g,o). 8 pad timesteps so recur's depth-4
// prefetch stays in-bounds.
__device__ float4 g_xg[(size_t)(T_ + 8) * B_ * H_];
// h[t][b][u] for the head pass.
__device__ float  g_h[(size_t)T_ * B_ * H_];

__device__ __forceinline__ float tanhx(float x) {
    float r; asm("tanh.approx.f32 %0,%1;" : "=f"(r) : "f"(x)); return r;
}
__device__ __forceinline__ float sigx(float x) {   // sigmoid via HW tanh
    return fmaf(0.5f, tanhx(0.5f * x), 0.5f);
}

// ---------------------------------------------------------------------------
// Kernel 1: xg = x @ W_ih^T + (b_ih+b_hh) for t < len[b].
// Thread = (column j 0..3, unit u, gate-pair p); 48 weight regs. x is staged
// through a 3-deep SHARED circular buffer, filled 2 iterations ahead by 24
// threads (1 LDG.128 + STS each) -> DRAM latency gets a 2-iteration window
// and the register pipeline buffer disappears (~75 regs -> 4 blocks/SM,
// 20 warps). Consumers read x via broadcast LDS.128 (29 cyc, covered).
// Coalesced float2 stores land directly in recur's [t][b][u] layout.
// ---------------------------------------------------------------------------
#define XG_CHUNK 64
__global__ __launch_bounds__(160, 4)
void xg_kernel(const float* __restrict__ x,
               const int*   __restrict__ lens,
               const float* __restrict__ Wih,
               const float* __restrict__ bih,
               const float* __restrict__ bhh)
{
    __shared__ float4 xs[3][4][6];            // 3-deep ring of 4 x-rows

    const int slab = blockIdx.x >> 3;         // 0..511 (4 b each)
    const int chn  = blockIdx.x & 7;          // 0..7
    const int t0   = chn * XG_CHUNK;
    const int b0   = slab * 4;

    const int lmax = lens[b0];                // max length in slab (sorted)
    if (t0 >= lmax) return;                   // whole block exits (pre-BAR)
    const int tend = min(t0 + XG_CHUNK, lmax);

    const int tid = threadIdx.x;
    const int j   = tid / 40;                 // column 0..3
    const int r   = tid % 40;
    const int u   = r >> 1;                   // unit 0..19
    const int p   = r & 1;                    // gate pair: 0=(i,f) 1=(g,o)
    const int b   = b0 + j;
    const int mylen = lens[b];

    const int g0 = 2 * p, g1 = 2 * p + 1;
    float w0[I_], w1[I_];
    #pragma unroll
    for (int k = 0; k < I_; k++) {
        w0[k] = Wih[(g0 * H_ + u) * I_ + k];
        w1[k] = Wih[(g1 * H_ + u) * I_ + k];
    }
    float2 bias;
    bias.x = bih[g0 * H_ + u] + bhh[g0 * H_ + u];
    bias.y = bih[g1 * H_ + u] + bhh[g1 * H_ + u];

    // staging role: threads 0..23 -> (column sc, quarter q)
    const int sc = tid / 6, sq = tid % 6;
    const float4* sbase = (const float4*)(x + (size_t)(b0 + sc) * I_) + sq;
    const size_t  xstr  = (size_t)B_ * I_ / 4;            // per-t, float4s

    // prologue: stage t0 -> buf0, t0+1 -> buf1 (clamped)
    if (tid < 24) {
        xs[0][sc][sq] = sbase[(size_t)t0 * xstr];
        xs[1][sc][sq] = sbase[(size_t)min(t0 + 1, T_ - 1) * xstr];
    }
    __syncthreads();

    const size_t ostr = (size_t)B_ * H_ * 2;              // per-t, float2s
    float2* op = (float2*)g_xg + ((size_t)t0 * B_ + b) * H_ * 2 + u * 2 + p;

    int cur = 0, wbuf = 2;
    for (int t = t0; t < tend; t++) {
        // stage x[t+2] into the write buffer (consumed 2 iterations later)
        if (tid < 24)
            xs[wbuf][sc][sq] = sbase[(size_t)min(t + 2, T_ - 1) * xstr];

        // consume x[t] from the current buffer
        const float4* xr = xs[cur][j];
        float4 v0 = xr[0], v1 = xr[1], v2 = xr[2];
        float4 v3 = xr[3], v4 = xr[4], v5 = xr[5];
        const float xv[I_] = { v0.x,v0.y,v0.z,v0.w, v1.x,v1.y,v1.z,v1.w,
                               v2.x,v2.y,v2.z,v2.w, v3.x,v3.y,v3.z,v3.w,
                               v4.x,v4.y,v4.z,v4.w, v5.x,v5.y,v5.z,v5.w };

        float ax0 = bias.x, ax1 = 0.0f, ay0 = bias.y, ay1 = 0.0f;
        #pragma unroll
        for (int k = 0; k < I_; k += 2) {     // two 12-deep chains per gate
            ax0 = fmaf(w0[k],   xv[k],   ax0);
            ax1 = fmaf(w0[k+1], xv[k+1], ax1);
            ay0 = fmaf(w1[k],   xv[k],   ay0);
            ay1 = fmaf(w1[k+1], xv[k+1], ay1);
        }

        if (t < mylen) *op = make_float2(ax0 + ax1, ay0 + ay1);
        op += ostr;

        cur  = (cur  == 2) ? 0 : cur  + 1;
        wbuf = (wbuf == 2) ? 0 : wbuf + 1;
        __syncthreads();                      // stage visible; reads done
    }
}

// ---------------------------------------------------------------------------
// Kernel 2: recurrence (R12 version — proven ~150us). One warp per batch
// element, t < len[b] only. Gate loads coalesced (320B/warp-step), depth-4
// rotated register prefetch. Past-mylen steps read in-bounds pad garbage
// but never store.
// ---------------------------------------------------------------------------
__global__ __launch_bounds__(128, 4)
void recur_kernel(const int*   __restrict__ lens,
                  const float* __restrict__ Whh)
{
    const int lane = threadIdx.x & 31;
    const int wid  = threadIdx.x >> 5;
    const int j    = blockIdx.x;
    const int b    = (wid < 2) ? (2*j + wid) : (2047 - 2*j - (wid - 2));
    const int uu   = (lane < H_) ? lane : 0;      // lanes 20..31 mirror u=0

    float wi[H_], wf[H_], wg[H_], wo[H_];
    #pragma unroll
    for (int k = 0; k < H_; k++) {
        wi[k] = Whh[(0*H_ + uu) * H_ + k];
        wf[k] = Whh[(1*H_ + uu) * H_ + k];
        wg[k] = Whh[(2*H_ + uu) * H_ + k];
        wo[k] = Whh[(3*H_ + uu) * H_ + k];
    }
    const int mylen = lens[b];                    // >= 1

    float h = 0.0f, c = 0.0f;

    const float4* xp = &g_xg[(size_t)b * H_ + uu];
    const size_t  xstride = (size_t)B_ * H_;
    float4 q0 = xp[0];
    float4 q1 = xp[xstride];
    float4 q2 = xp[2*xstride];
    float4 q3 = xp[3*xstride];
    xp += 4 * xstride;                            // next refill row

    float* hp = &g_h[(size_t)b * H_ + lane];

    #define RSTEP(QBUF, TOFF)                                            \
    {                                                                    \
        float ai = QBUF.x, af = QBUF.y, ag = QBUF.z, ao = QBUF.w;        \
        _Pragma("unroll")                                                \
        for (int k = 0; k < H_; k++) {                                   \
            float hk = __shfl_sync(0xffffffffu, h, k);                   \
            ai = fmaf(wi[k], hk, ai);                                    \
            af = fmaf(wf[k], hk, af);                                    \
            ag = fmaf(wg[k], hk, ag);                                    \
            ao = fmaf(wo[k], hk, ao);                                    \
        }                                                                \
        c = fmaf(sigx(af), c, sigx(ai) * tanhx(ag));                     \
        h = sigx(ao) * tanhx(c);                                         \
        if (lane < H_ && (t + TOFF) < mylen)                             \
            hp[(size_t)(t + TOFF) * (B_ * H_)] = h;                      \
        QBUF = *xp;                               /* refill t+TOFF+4 */  \
        xp += xstride;                                                   \
    }

    for (int t = 0; t < mylen; t += 4) {
        RSTEP(q0, 0)
        RSTEP(q1, 1)
        RSTEP(q2, 2)
        RSTEP(q3, 3)
    }
    #undef RSTEP
}

// ---------------------------------------------------------------------------
// Kernel 3: heads + padding over the full [T, B] grid.
// ---------------------------------------------------------------------------
__global__ __launch_bounds__(256)
void head_kernel(const int*   __restrict__ lens,
                 const float* __restrict__ Wa,
                 const float* __restrict__ ba,
                 const float* __restrict__ Wb,
                 const float* __restrict__ bb,
                 float* __restrict__ out)
{
    const int idx = blockIdx.x * 256 + threadIdx.x;   // t*B + b
    const int b   = idx & (B_ - 1);
    const int t   = idx >> 11;

    float za = ba[0], zb = bb[0];
    if (t < lens[b]) {
        float4 hq[5];
        const float4* hp = (const float4*)&g_h[(size_t)idx * H_];
        #pragma unroll
        for (int q = 0; q < 5; q++) hq[q] = hp[q];
        const float* hv = (const float*)hq;
        #pragma unroll
        for (int k = 0; k < H_; k++) {
            za = fmaf(hv[k], Wa[k], za);
            zb = fmaf(hv[k], Wb[k], zb);
        }
    }
    out[idx] = __expf(za);
    out[(size_t)T_ * B_ + idx] =
        fmaxf(zb, 0.0f) + __logf(1.0f + __expf(-fabsf(zb)));
}

extern "C" void kernel_launch(void* const* d_in, const int* in_sizes, int n_in,
                              void* d_out, int out_size)
{
    const float *x = 0, *Wih = 0, *Whh = 0, *bih = 0, *bhh = 0;
    const float *Wa = 0, *ba = 0, *Wb = 0, *bb = 0;
    const int *lens = 0;
    int seen80 = 0, seen20 = 0, seen1 = 0;
    for (int i = 0; i < n_in; i++) {
        int s = in_sizes[i];
        if      (s == T_ * B_ * I_) x    = (const float*)d_in[i];
        else if (s == B_)           lens = (const int*)d_in[i];
        else if (s == 4*H_ * I_)    Wih  = (const float*)d_in[i];
        else if (s == 4*H_ * H_)    Whh  = (const float*)d_in[i];
        else if (s == 4*H_) { if (seen80++ == 0) bih = (const float*)d_in[i]; else bhh = (const float*)d_in[i]; }
        else if (s == H_)   { if (seen20++ == 0) Wa  = (const float*)d_in[i]; else Wb  = (const float*)d_in[i]; }
        else if (s == 1)    { if (seen1++  == 0) ba  = (const float*)d_in[i]; else bb  = (const float*)d_in[i]; }
    }

    float* out = (float*)d_out;
    xg_kernel<<<512 * 8, 160>>>(x, lens, Wih, bih, bhh);
    recur_kernel<<<512, 128>>>(lens, Whh);
    head_kernel<<<(T_ * B_) / 256, 256>>>(lens, Wa, ba, Wb, bb, out);
}

// round 15
// speedup vs baseline: 1.0868x; 1.0042x over previous
#include <cuda_runtime.h>
#include <math.h>

#define T_  512
#define B_  2048
#define I_  24
#define H_  20

// Scratch xg[t][b][u] = float4(i,f,g,o). 8 pad timesteps so recur's depth-2
// prefetch stays in-bounds.
__device__ float4 g_xg[(size_t)(T_ + 8) * B_ * H_];
// h[t][b][u] for the head pass.
__device__ float  g_h[(size_t)T_ * B_ * H_];

__device__ __forceinline__ float tanhx(float x) {
    float r; asm("tanh.approx.f32 %0,%1;" : "=f"(r) : "f"(x)); return r;
}
__device__ __forceinline__ float sigx(float x) {   // sigmoid via HW tanh
    return fmaf(0.5f, tanhx(0.5f * x), 0.5f);
}

// ---------------------------------------------------------------------------
// Kernel 1 (R12, frozen — 133.5us measured): xg = x @ W_ih^T + (b_ih+b_hh)
// for t < len[b]. Thread = (column j 0..3, unit u, gate-pair p); 48 weight
// regs; software-pipelined x[t+1] register buffer; coalesced float2 stores
// into recur's [t][b][u] layout.
// ---------------------------------------------------------------------------
#define XG_CHUNK 64
__global__ __launch_bounds__(160, 3)
void xg_kernel(const float* __restrict__ x,
               const int*   __restrict__ lens,
               const float* __restrict__ Wih,
               const float* __restrict__ bih,
               const float* __restrict__ bhh)
{
    const int slab = blockIdx.x >> 3;         // 0..511 (4 b each)
    const int chn  = blockIdx.x & 7;          // 0..7
    const int t0   = chn * XG_CHUNK;
    const int b0   = slab * 4;

    const int lmax = lens[b0];                // max length in slab (sorted)
    if (t0 >= lmax) return;                   // whole chunk masked
    const int tend = min(t0 + XG_CHUNK, lmax);

    const int tid = threadIdx.x;
    const int j   = tid / 40;                 // column 0..3
    const int r   = tid % 40;
    const int u   = r >> 1;                   // unit 0..19
    const int p   = r & 1;                    // gate pair: 0=(i,f) 1=(g,o)
    const int b   = b0 + j;
    const int mylen = lens[b];

    const int g0 = 2 * p, g1 = 2 * p + 1;
    float w0[I_], w1[I_];
    #pragma unroll
    for (int k = 0; k < I_; k++) {
        w0[k] = Wih[(g0 * H_ + u) * I_ + k];
        w1[k] = Wih[(g1 * H_ + u) * I_ + k];
    }
    float2 bias;
    bias.x = bih[g0 * H_ + u] + bhh[g0 * H_ + u];
    bias.y = bih[g1 * H_ + u] + bhh[g1 * H_ + u];

    const size_t xstr = (size_t)B_ * I_ / 4;              // per-t, in float4s
    const size_t ostr = (size_t)B_ * H_ * 2;              // per-t, in float2s
    const float4* xbase = (const float4*)(x + (size_t)b * I_);
    float2* op = (float2*)g_xg + ((size_t)t0 * B_ + b) * H_ * 2 + u * 2 + p;

    float4 c0, c1, c2, c3, c4, c5;            // current x[t]
    {
        const float4* pc = xbase + (size_t)t0 * xstr;
        c0 = pc[0]; c1 = pc[1]; c2 = pc[2];
        c3 = pc[3]; c4 = pc[4]; c5 = pc[5];
    }

    #pragma unroll 2
    for (int t = t0; t < tend; t++) {
        const float4* pn = xbase + (size_t)min(t + 1, T_ - 1) * xstr;
        float4 n0 = pn[0], n1 = pn[1], n2 = pn[2];
        float4 n3 = pn[3], n4 = pn[4], n5 = pn[5];

        const float xv[I_] = { c0.x,c0.y,c0.z,c0.w, c1.x,c1.y,c1.z,c1.w,
                               c2.x,c2.y,c2.z,c2.w, c3.x,c3.y,c3.z,c3.w,
                               c4.x,c4.y,c4.z,c4.w, c5.x,c5.y,c5.z,c5.w };
        float2 a = bias;
        #pragma unroll
        for (int k = 0; k < I_; k++) {
            a.x = fmaf(w0[k], xv[k], a.x);
            a.y = fmaf(w1[k], xv[k], a.y);
        }

        if (t < mylen) *op = a;               // coalesced float2 store
        op += ostr;

        c0 = n0; c1 = n1; c2 = n2; c3 = n3; c4 = n4; c5 = n5;
    }
}

// ---------------------------------------------------------------------------
// Kernel 2: recurrence, one warp per batch element, t < len[b] only.
// NEW: h broadcast via per-warp DOUBLE-BUFFERED shared slot instead of 20
// SHFLs — per step: 1 predicated STS + 1 syncwarp + 5 broadcast LDS.128.
// MIO ops/step 20 -> 7; FMA chains split even/odd (40-cyc instead of 80).
// Gate loads coalesced, depth-2 rotated register prefetch (reg budget).
// ---------------------------------------------------------------------------
__global__ __launch_bounds__(128, 4)
void recur_kernel(const int*   __restrict__ lens,
                  const float* __restrict__ Whh)
{
    __shared__ __align__(16) float hsm[4][2][24];   // [warp][slot][unit pad]

    const int lane = threadIdx.x & 31;
    const int wid  = threadIdx.x >> 5;
    const int j    = blockIdx.x;
    const int b    = (wid < 2) ? (2*j + wid) : (2047 - 2*j - (wid - 2));
    const int uu   = (lane < H_) ? lane : 0;      // lanes 20..31 mirror u=0

    float wi[H_], wf[H_], wg[H_], wo[H_];
    #pragma unroll
    for (int k = 0; k < H_; k++) {
        wi[k] = Whh[(0*H_ + uu) * H_ + k];
        wf[k] = Whh[(1*H_ + uu) * H_ + k];
        wg[k] = Whh[(2*H_ + uu) * H_ + k];
        wo[k] = Whh[(3*H_ + uu) * H_ + k];
    }
    const int mylen = lens[b];                    // >= 1

    float c = 0.0f;

    const float4* xp = &g_xg[(size_t)b * H_ + uu];
    const size_t  xstride = (size_t)B_ * H_;
    float4 q0 = xp[0];
    float4 q1 = xp[xstride];
    xp += 2 * xstride;                            // next refill row

    float* hp = &g_h[(size_t)b * H_ + lane];

    if (lane < H_) hsm[wid][0][lane] = 0.0f;      // h(-1) = 0 into slot 0
    __syncwarp();

    #define RSTEP(QBUF, TOFF)                                            \
    {                                                                    \
        const float4* hq = (const float4*)hsm[wid][(t + TOFF) & 1];      \
        float4 h0 = hq[0], h1 = hq[1], h2 = hq[2], h3 = hq[3], h4 = hq[4]; \
        const float hv[H_] = { h0.x,h0.y,h0.z,h0.w, h1.x,h1.y,h1.z,h1.w, \
                               h2.x,h2.y,h2.z,h2.w, h3.x,h3.y,h3.z,h3.w, \
                               h4.x,h4.y,h4.z,h4.w };                    \
        float ai0 = QBUF.x, af0 = QBUF.y, ag0 = QBUF.z, ao0 = QBUF.w;    \
        float ai1 = 0.f, af1 = 0.f, ag1 = 0.f, ao1 = 0.f;                \
        _Pragma("unroll")                                                \
        for (int k = 0; k < H_; k += 2) {                                \
            ai0 = fmaf(wi[k],   hv[k],   ai0);                           \
            ai1 = fmaf(wi[k+1], hv[k+1], ai1);                           \
            af0 = fmaf(wf[k],   hv[k],   af0);                           \
            af1 = fmaf(wf[k+1], hv[k+1], af1);                           \
            ag0 = fmaf(wg[k],   hv[k],   ag0);                           \
            ag1 = fmaf(wg[k+1], hv[k+1], ag1);                           \
            ao0 = fmaf(wo[k],   hv[k],   ao0);                           \
            ao1 = fmaf(wo[k+1], hv[k+1], ao1);                           \
        }                                                                \
        float ai = ai0 + ai1, af = af0 + af1;                            \
        float ag = ag0 + ag1, ao = ao0 + ao1;                            \
        c = fmaf(sigx(af), c, sigx(ai) * tanhx(ag));                     \
        float h = sigx(ao) * tanhx(c);                                   \
        if (lane < H_) {                                                 \
            hsm[wid][(t + TOFF + 1) & 1][lane] = h;                      \
            if ((t + TOFF) < mylen)                                      \
                hp[(size_t)(t + TOFF) * (B_ * H_)] = h;                  \
        }                                                                \
        __syncwarp();                                                    \
        QBUF = *xp;                               /* refill t+TOFF+2 */  \
        xp += xstride;                                                   \
    }

    for (int t = 0; t < mylen; t += 2) {
        RSTEP(q0, 0)
        RSTEP(q1, 1)
    }
    #undef RSTEP
}

// ---------------------------------------------------------------------------
// Kernel 3: heads + padding over the full [T, B] grid.
// ---------------------------------------------------------------------------
__global__ __launch_bounds__(256)
void head_kernel(const int*   __restrict__ lens,
                 const float* __restrict__ Wa,
                 const float* __restrict__ ba,
                 const float* __restrict__ Wb,
                 const float* __restrict__ bb,
                 float* __restrict__ out)
{
    const int idx = blockIdx.x * 256 + threadIdx.x;   // t*B + b
    const int b   = idx & (B_ - 1);
    const int t   = idx >> 11;

    float za = ba[0], zb = bb[0];
    if (t < lens[b]) {
        float4 hq[5];
        const float4* hp = (const float4*)&g_h[(size_t)idx * H_];
        #pragma unroll
        for (int q = 0; q < 5; q++) hq[q] = hp[q];
        const float* hv = (const float*)hq;
        #pragma unroll
        for (int k = 0; k < H_; k++) {
            za = fmaf(hv[k], Wa[k], za);
            zb = fmaf(hv[k], Wb[k], zb);
        }
    }
    out[idx] = __expf(za);
    out[(size_t)T_ * B_ + idx] =
        fmaxf(zb, 0.0f) + __logf(1.0f + __expf(-fabsf(zb)));
}

extern "C" void kernel_launch(void* const* d_in, const int* in_sizes, int n_in,
                              void* d_out, int out_size)
{
    const float *x = 0, *Wih = 0, *Whh = 0, *bih = 0, *bhh = 0;
    const float *Wa = 0, *ba = 0, *Wb = 0, *bb = 0;
    const int *lens = 0;
    int seen80 = 0, seen20 = 0, seen1 = 0;
    for (int i = 0; i < n_in; i++) {
        int s = in_sizes[i];
        if      (s == T_ * B_ * I_) x    = (const float*)d_in[i];
        else if (s == B_)           lens = (const int*)d_in[i];
        else if (s == 4*H_ * I_)    Wih  = (const float*)d_in[i];
        else if (s == 4*H_ * H_)    Whh  = (const float*)d_in[i];
        else if (s == 4*H_) { if (seen80++ == 0) bih = (const float*)d_in[i]; else bhh = (const float*)d_in[i]; }
        else if (s == H_)   { if (seen20++ == 0) Wa  = (const float*)d_in[i]; else Wb  = (const float*)d_in[i]; }
        else if (s == 1)    { if (seen1++  == 0) ba  = (const float*)d_in[i]; else bb  = (const float*)d_in[i]; }
    }

    float* out = (float*)d_out;
    xg_kernel<<<512 * 8, 160>>>(x, lens, Wih, bih, bhh);
    recur_kernel<<<512, 128>>>(lens, Whh);
    head_kernel<<<(T_ * B_) / 256, 256>>>(lens, Wa, ba, Wb, bb, out);
}

// round 17
// speedup vs baseline: 1.4749x; 1.3571x over previous
#include <cuda_runtime.h>
#include <math.h>

#define T_  512
#define B_  2048
#define I_  24
#define H_  20

// Scratch xg[t][b][u] = float4(i,f,g,o). 8 pad timesteps so recur's depth-4
// prefetch stays in-bounds.
__device__ float4 g_xg[(size_t)(T_ + 8) * B_ * H_];
// h[t][b][u] for the head pass.
__device__ float  g_h[(size_t)T_ * B_ * H_];

__device__ __forceinline__ float tanhx(float x) {
    float r; asm("tanh.approx.f32 %0,%1;" : "=f"(r) : "f"(x)); return r;
}
__device__ __forceinline__ float sigx(float x) {   // sigmoid via HW tanh
    return fmaf(0.5f, tanhx(0.5f * x), 0.5f);
}

// ---------------------------------------------------------------------------
// Kernel 1: xg = x @ W_ih^T + (b_ih+b_hh) for t < len[b].
// R12 compute (thread = column j x unit u x gate-pair p; 48 weight regs;
// coalesced float2 stores into recur's [t][b][u] layout), but x is staged
// by cp.async (LDGSTS: no LDG->STS register chain) into an 8-slot shared
// ring SIX iterations ahead. Two timesteps per stage group -> one
// __syncthreads per 2 t. Dropping the register pipeline buffer cuts regs
// (~90) -> 4 blocks/SM (20 warps, +33% latency coverage).
// ---------------------------------------------------------------------------
#define XG_CHUNK 64
#define RING 8

__device__ __forceinline__ void cp16(void* smem_dst, const void* gmem_src) {
    unsigned s = (unsigned)__cvta_generic_to_shared(smem_dst);
    asm volatile("cp.async.cg.shared.global [%0], [%1], 16;\n"
                 :: "r"(s), "l"(gmem_src));
}
__device__ __forceinline__ void cp_commit() {
    asm volatile("cp.async.commit_group;\n");
}
template<int N> __device__ __forceinline__ void cp_wait() {
    asm volatile("cp.async.wait_group %0;\n" :: "n"(N));
}

__global__ __launch_bounds__(160, 4)
void xg_kernel(const float* __restrict__ x,
               const int*   __restrict__ lens,
               const float* __restrict__ Wih,
               const float* __restrict__ bih,
               const float* __restrict__ bhh)
{
    __shared__ __align__(16) float4 xs[RING][4][6];   // 3 KB ring

    const int slab = blockIdx.x >> 3;         // 0..511 (4 b each)
    const int chn  = blockIdx.x & 7;          // 0..7
    const int t0   = chn * XG_CHUNK;
    const int b0   = slab * 4;

    const int lmax = lens[b0];                // max length in slab (sorted)
    if (t0 >= lmax) return;                   // whole block exits (pre-BAR)
    const int tend = min(t0 + XG_CHUNK, lmax);

    const int tid = threadIdx.x;
    const int j   = tid / 40;                 // column 0..3
    const int r   = tid % 40;
    const int u   = r >> 1;                   // unit 0..19
    const int p   = r & 1;                    // gate pair: 0=(i,f) 1=(g,o)
    const int b   = b0 + j;
    const int mylen = lens[b];

    const int g0 = 2 * p, g1 = 2 * p + 1;
    float w0[I_], w1[I_];
    #pragma unroll
    for (int k = 0; k < I_; k++) {
        w0[k] = Wih[(g0 * H_ + u) * I_ + k];
        w1[k] = Wih[(g1 * H_ + u) * I_ + k];
    }
    float2 bias;
    bias.x = bih[g0 * H_ + u] + bhh[g0 * H_ + u];
    bias.y = bih[g1 * H_ + u] + bhh[g1 * H_ + u];

    // staging role: threads 0..23 -> (column sc, quarter sq)
    const int  sc = tid / 6, sq = tid % 6;
    const bool stager = (tid < 24);
    const float* sgbase = x + (size_t)(b0 + sc) * I_ + sq * 4;
    const size_t sgstr  = (size_t)B_ * I_;                // per-t, floats

    // prologue: stage t0 .. t0+5 into slots 0..5 (one group per t)
    #pragma unroll
    for (int s = 0; s < 6; s++) {
        if (stager) {
            int tt = min(t0 + s, T_ - 1);
            cp16(&xs[s][sc][sq], sgbase + (size_t)tt * sgstr);
        }
        cp_commit();
    }
    cp_wait<4>();            // t0, t0+1 complete
    __syncthreads();

    const size_t ostr = (size_t)B_ * H_ * 2;              // per-t, float2s
    float2* op = (float2*)g_xg + ((size_t)t0 * B_ + b) * H_ * 2 + u * 2 + p;

    for (int t = t0; t < tend; t += 2) {
        // stage t+6, t+7 (ring slots (t+6)%8, (t+7)%8)
        if (stager) {
            int ta = min(t + 6, T_ - 1);
            cp16(&xs[(t + 6) & (RING - 1)][sc][sq], sgbase + (size_t)ta * sgstr);
        }
        cp_commit();
        if (stager) {
            int tb = min(t + 7, T_ - 1);
            cp16(&xs[(t + 7) & (RING - 1)][sc][sq], sgbase + (size_t)tb * sgstr);
        }
        cp_commit();
        cp_wait<4>();        // everything through t+3 complete (need t+1)
        __syncthreads();     // staged data visible block-wide; old reads done

        // ---- consume t ----
        {
            const float4* xr = xs[t & (RING - 1)][j];
            float4 v0 = xr[0], v1 = xr[1], v2 = xr[2];
            float4 v3 = xr[3], v4 = xr[4], v5 = xr[5];
            const float xv[I_] = { v0.x,v0.y,v0.z,v0.w, v1.x,v1.y,v1.z,v1.w,
                                   v2.x,v2.y,v2.z,v2.w, v3.x,v3.y,v3.z,v3.w,
                                   v4.x,v4.y,v4.z,v4.w, v5.x,v5.y,v5.z,v5.w };
            float ax0 = bias.x, ax1 = 0.0f, ay0 = bias.y, ay1 = 0.0f;
            #pragma unroll
            for (int k = 0; k < I_; k += 2) {
                ax0 = fmaf(w0[k],   xv[k],   ax0);
                ax1 = fmaf(w0[k+1], xv[k+1], ax1);
                ay0 = fmaf(w1[k],   xv[k],   ay0);
                ay1 = fmaf(w1[k+1], xv[k+1], ay1);
            }
            if (t < mylen) *op = make_float2(ax0 + ax1, ay0 + ay1);
        }
        // ---- consume t+1 ----
        {
            const float4* xr = xs[(t + 1) & (RING - 1)][j];
            float4 v0 = xr[0], v1 = xr[1], v2 = xr[2];
            float4 v3 = xr[3], v4 = xr[4], v5 = xr[5];
            const float xv[I_] = { v0.x,v0.y,v0.z,v0.w, v1.x,v1.y,v1.z,v1.w,
                                   v2.x,v2.y,v2.z,v2.w, v3.x,v3.y,v3.z,v3.w,
                                   v4.x,v4.y,v4.z,v4.w, v5.x,v5.y,v5.z,v5.w };
            float ax0 = bias.x, ax1 = 0.0f, ay0 = bias.y, ay1 = 0.0f;
            #pragma unroll
            for (int k = 0; k < I_; k += 2) {
                ax0 = fmaf(w0[k],   xv[k],   ax0);
                ax1 = fmaf(w0[k+1], xv[k+1], ax1);
                ay0 = fmaf(w1[k],   xv[k],   ay0);
                ay1 = fmaf(w1[k+1], xv[k+1], ay1);
            }
            if (t + 1 < mylen) op[ostr] = make_float2(ax0 + ax1, ay0 + ay1);
        }
        op += 2 * ostr;
    }
}

// ---------------------------------------------------------------------------
// Kernel 2: recurrence (R12 exact — proven ~150us). One warp per batch
// element, t < len[b] only; SHFL h-broadcast; Whh in regs; depth-4 rotated
// register gate prefetch; past-mylen steps never store.
// ---------------------------------------------------------------------------
__global__ __launch_bounds__(128, 4)
void recur_kernel(const int*   __restrict__ lens,
                  const float* __restrict__ Whh)
{
    const int lane = threadIdx.x & 31;
    const int wid  = threadIdx.x >> 5;
    const int j    = blockIdx.x;
    const int b    = (wid < 2) ? (2*j + wid) : (2047 - 2*j - (wid - 2));
    const int uu   = (lane < H_) ? lane : 0;      // lanes 20..31 mirror u=0

    float wi[H_], wf[H_], wg[H_], wo[H_];
    #pragma unroll
    for (int k = 0; k < H_; k++) {
        wi[k] = Whh[(0*H_ + uu) * H_ + k];
        wf[k] = Whh[(1*H_ + uu) * H_ + k];
        wg[k] = Whh[(2*H_ + uu) * H_ + k];
        wo[k] = Whh[(3*H_ + uu) * H_ + k];
    }
    const int mylen = lens[b];                    // >= 1

    float h = 0.0f, c = 0.0f;

    const float4* xp = &g_xg[(size_t)b * H_ + uu];
    const size_t  xstride = (size_t)B_ * H_;
    float4 q0 = xp[0];
    float4 q1 = xp[xstride];
    float4 q2 = xp[2*xstride];
    float4 q3 = xp[3*xstride];
    xp += 4 * xstride;                            // next refill row

    float* hp = &g_h[(size_t)b * H_ + lane];

    #define RSTEP(QBUF, TOFF)                                            \
    {                                                                    \
        float ai = QBUF.x, af = QBUF.y, ag = QBUF.z, ao = QBUF.w;        \
        _Pragma("unroll")                                                \
        for (int k = 0; k < H_; k++) {                                   \
            float hk = __shfl_sync(0xffffffffu, h, k);                   \
            ai = fmaf(wi[k], hk, ai);                                    \
            af = fmaf(wf[k], hk, af);                                    \
            ag = fmaf(wg[k], hk, ag);                                    \
            ao = fmaf(wo[k], hk, ao);                                    \
        }                                                                \
        c = fmaf(sigx(af), c, sigx(ai) * tanhx(ag));                     \
        h = sigx(ao) * tanhx(c);                                         \
        if (lane < H_ && (t + TOFF) < mylen)                             \
            hp[(size_t)(t + TOFF) * (B_ * H_)] = h;                      \
        QBUF = *xp;                               /* refill t+TOFF+4 */  \
        xp += xstride;                                                   \
    }

    for (int t = 0; t < mylen; t += 4) {
        RSTEP(q0, 0)
        RSTEP(q1, 1)
        RSTEP(q2, 2)
        RSTEP(q3, 3)
    }
    #undef RSTEP
}

// ---------------------------------------------------------------------------
// Kernel 3: heads + padding over the full [T, B] grid.
// ---------------------------------------------------------------------------
__global__ __launch_bounds__(256)
void head_kernel(const int*   __restrict__ lens,
                 const float* __restrict__ Wa,
                 const float* __restrict__ ba,
                 const float* __restrict__ Wb,
                 const float* __restrict__ bb,
                 float* __restrict__ out)
{
    const int idx = blockIdx.x * 256 + threadIdx.x;   // t*B + b
    const int b   = idx & (B_ - 1);
    const int t   = idx >> 11;

    float za = ba[0], zb = bb[0];
    if (t < lens[b]) {
        float4 hq[5];
        const float4* hp = (const float4*)&g_h[(size_t)idx * H_];
        #pragma unroll
        for (int q = 0; q < 5; q++) hq[q] = hp[q];
        const float* hv = (const float*)hq;
        #pragma unroll
        for (int k = 0; k < H_; k++) {
            za = fmaf(hv[k], Wa[k], za);
            zb = fmaf(hv[k], Wb[k], zb);
        }
    }
    out[idx] = __expf(za);
    out[(size_t)T_ * B_ + idx] =
        fmaxf(zb, 0.0f) + __logf(1.0f + __expf(-fabsf(zb)));
}

extern "C" void kernel_launch(void* const* d_in, const int* in_sizes, int n_in,
                              void* d_out, int out_size)
{
    const float *x = 0, *Wih = 0, *Whh = 0, *bih = 0, *bhh = 0;
    const float *Wa = 0, *ba = 0, *Wb = 0, *bb = 0;
    const int *lens = 0;
    int seen80 = 0, seen20 = 0, seen1 = 0;
    for (int i = 0; i < n_in; i++) {
        int s = in_sizes[i];
        if      (s == T_ * B_ * I_) x    = (const float*)d_in[i];
        else if (s == B_)           lens = (const int*)d_in[i];
        else if (s == 4*H_ * I_)    Wih  = (const float*)d_in[i];
        else if (s == 4*H_ * H_)    Whh  = (const float*)d_in[i];
        else if (s == 4*H_) { if (seen80++ == 0) bih = (const float*)d_in[i]; else bhh = (const float*)d_in[i]; }
        else if (s == H_)   { if (seen20++ == 0) Wa  = (const float*)d_in[i]; else Wb  = (const float*)d_in[i]; }
        else if (s == 1)    { if (seen1++  == 0) ba  = (const float*)d_in[i]; else bb  = (const float*)d_in[i]; }
    }

    float* out = (float*)d_out;
    xg_kernel<<<512 * 8, 160>>>(x, lens, Wih, bih, bhh);
    recur_kernel<<<512, 128>>>(lens, Whh);
    head_kernel<<<(T_ * B_) / 256, 256>>>(lens, Wa, ba, Wb, bb, out);
}